// round 4
// baseline (speedup 1.0000x reference)
#include <cuda_runtime.h>
#include <math.h>
#include <stdint.h>

// CosineAttention: B=64, L=4096, D=1024
//   q = l2norm(query); k = l2norm(keys); scores = k @ q; softmax over L with mask.
//
// Kernel 1: one warp per (b,l) key row. Streams keys once (1 GiB), computes
//           dot(k,q) and dot(k,k) simultaneously, writes raw score
//           s = dot / max(||k||, eps) into d_out (used as scratch).
// Kernel 2: one block per batch row. Computes ||q||, scales, masks, softmax,
//           rewrites d_out in place.
//
// Inputs bound BY ELEMENT COUNT (unique per tensor): query=65536,
// keys=268435456, mask=262144. Mask is int32 (harness converts bool->int32;
// rel_err was exactly sqrt(3), the uint8-misread fingerprint).

#define B 64
#define L 4096
#define D 1024
#define EPS 1e-12f

#define WARPS_PER_BLOCK 8
#define THREADS1 (WARPS_PER_BLOCK * 32)

__global__ __launch_bounds__(THREADS1)
void cosatt_scores_kernel(const float* __restrict__ query,
                          const float* __restrict__ keys,
                          float* __restrict__ scores)
{
    const int b    = blockIdx.y;
    const int warp = threadIdx.x >> 5;
    const int lane = threadIdx.x & 31;
    const int l    = blockIdx.x * WARPS_PER_BLOCK + warp;

    const float4* __restrict__ krow =
        reinterpret_cast<const float4*>(keys + ((size_t)b * L + l) * D);
    const float4* __restrict__ qrow =
        reinterpret_cast<const float4*>(query + (size_t)b * D);

    float dot = 0.f;
    float kk  = 0.f;

    // D=1024 floats = 256 float4 per row; 32 lanes x 8 iterations, fully
    // unrolled -> 8 independent LDG.128 in flight per lane (MLP ~8).
    #pragma unroll
    for (int i = 0; i < 8; ++i) {
        const int idx = i * 32 + lane;
        float4 kv = krow[idx];
        float4 qv = qrow[idx];
        dot = fmaf(kv.x, qv.x, dot);
        dot = fmaf(kv.y, qv.y, dot);
        dot = fmaf(kv.z, qv.z, dot);
        dot = fmaf(kv.w, qv.w, dot);
        kk  = fmaf(kv.x, kv.x, kk);
        kk  = fmaf(kv.y, kv.y, kk);
        kk  = fmaf(kv.z, kv.z, kk);
        kk  = fmaf(kv.w, kv.w, kk);
    }

    // warp reduction
    #pragma unroll
    for (int off = 16; off > 0; off >>= 1) {
        dot += __shfl_xor_sync(0xffffffffu, dot, off);
        kk  += __shfl_xor_sync(0xffffffffu, kk,  off);
    }

    if (lane == 0) {
        float kn = fmaxf(sqrtf(kk), EPS);
        scores[(size_t)b * L + l] = dot / kn;
    }
}

#define THREADS2 256
#define PER_THREAD (L / THREADS2)   // 16 scores per thread

__global__ __launch_bounds__(THREADS2)
void cosatt_softmax_kernel(const float* __restrict__ query,
                           const int* __restrict__ mask,
                           float* __restrict__ scores /* in/out */)
{
    const int b   = blockIdx.x;
    const int tid = threadIdx.x;

    __shared__ float red[THREADS2 / 32];
    __shared__ float s_qn;

    // ---- ||q|| for this batch row (1024 elems, 4 per thread) ----
    {
        const float* q = query + (size_t)b * D;
        float qq = 0.f;
        #pragma unroll
        for (int i = 0; i < D / THREADS2; ++i) {
            float v = q[i * THREADS2 + tid];
            qq = fmaf(v, v, qq);
        }
        #pragma unroll
        for (int off = 16; off > 0; off >>= 1)
            qq += __shfl_xor_sync(0xffffffffu, qq, off);
        if ((tid & 31) == 0) red[tid >> 5] = qq;
        __syncthreads();
        if (tid < 32) {
            float v = (tid < THREADS2 / 32) ? red[tid] : 0.f;
            #pragma unroll
            for (int off = 16; off > 0; off >>= 1)
                v += __shfl_xor_sync(0xffffffffu, v, off);
            if (tid == 0) s_qn = fmaxf(sqrtf(v), EPS);
        }
        __syncthreads();
    }
    const float inv_qn = 1.0f / s_qn;

    // ---- load, scale, mask ----
    float v[PER_THREAD];
    float local_max = -INFINITY;
    const float* srow = scores + (size_t)b * L;
    const int*   mrow = mask   + (size_t)b * L;

    #pragma unroll
    for (int i = 0; i < PER_THREAD; ++i) {
        const int idx = i * THREADS2 + tid;
        float s = srow[idx] * inv_qn;
        v[i] = (mrow[idx] != 0) ? s : -INFINITY;
        local_max = fmaxf(local_max, v[i]);
    }

    // ---- block max ----
    #pragma unroll
    for (int off = 16; off > 0; off >>= 1)
        local_max = fmaxf(local_max, __shfl_xor_sync(0xffffffffu, local_max, off));
    if ((tid & 31) == 0) red[tid >> 5] = local_max;
    __syncthreads();
    __shared__ float s_max;
    if (tid < 32) {
        float m = (tid < THREADS2 / 32) ? red[tid] : -INFINITY;
        #pragma unroll
        for (int off = 16; off > 0; off >>= 1)
            m = fmaxf(m, __shfl_xor_sync(0xffffffffu, m, off));
        if (tid == 0) s_max = m;
    }
    __syncthreads();
    const float row_max = s_max;

    // ---- exp + block sum ----
    float local_sum = 0.f;
    #pragma unroll
    for (int i = 0; i < PER_THREAD; ++i) {
        float e = __expf(v[i] - row_max);   // exp(-inf - m) = 0 for masked
        v[i] = e;
        local_sum += e;
    }
    #pragma unroll
    for (int off = 16; off > 0; off >>= 1)
        local_sum += __shfl_xor_sync(0xffffffffu, local_sum, off);
    __syncthreads();   // red[] reuse
    if ((tid & 31) == 0) red[tid >> 5] = local_sum;
    __syncthreads();
    __shared__ float s_sum;
    if (tid < 32) {
        float sm = (tid < THREADS2 / 32) ? red[tid] : 0.f;
        #pragma unroll
        for (int off = 16; off > 0; off >>= 1)
            sm += __shfl_xor_sync(0xffffffffu, sm, off);
        if (tid == 0) s_sum = sm;
    }
    __syncthreads();
    const float inv_sum = 1.0f / s_sum;

    float* orow = scores + (size_t)b * L;
    #pragma unroll
    for (int i = 0; i < PER_THREAD; ++i)
        orow[i * THREADS2 + tid] = v[i] * inv_sum;
}

extern "C" void kernel_launch(void* const* d_in, const int* in_sizes, int n_in,
                              void* d_out, int out_size)
{
    // Bind inputs by unique element count (robust to metadata ordering).
    const float* query = nullptr;  // B*D   = 65536
    const float* keys  = nullptr;  // B*L*D = 268435456
    const int*   mask  = nullptr;  // B*L   = 262144 (int32)

    for (int i = 0; i < n_in; ++i) {
        if (in_sizes[i] == B * D)      query = (const float*)d_in[i];
        else if (in_sizes[i] == B * L) mask  = (const int*)d_in[i];
        else                           keys  = (const float*)d_in[i];
    }

    float* out = (float*)d_out;  // [B, L] float32

    dim3 grid1(L / WARPS_PER_BLOCK, B);
    cosatt_scores_kernel<<<grid1, THREADS1>>>(query, keys, out);
    cosatt_softmax_kernel<<<B, THREADS2>>>(query, mask, out);
}

// round 5
// speedup vs baseline: 1.0109x; 1.0109x over previous
#include <cuda_runtime.h>
#include <math.h>
#include <stdint.h>

// CosineAttention: B=64, L=4096, D=1024
//   q = l2norm(query); k = l2norm(keys); scores = k @ q; softmax over L with mask.
//
// Kernel 1: one warp per (b,l) key row. Streams keys once (1 GiB, __ldcs
//           evict-first), computes dot(k,q) and dot(k,k) in one pass, writes
//           raw score s = dot / max(||k||, eps) into d_out (scratch).
// Kernel 2: one 1024-thread block per batch row. Computes ||q||, scales,
//           masks (int32), softmax, rewrites d_out in place. Vectorized
//           float4/int4 loads, PER_THREAD=4 to shorten dependency chains.
//
// Inputs bound BY ELEMENT COUNT: query=65536, keys=268435456, mask=262144(int32).

#define B 64
#define L 4096
#define D 1024
#define EPS 1e-12f

#define WARPS_PER_BLOCK 8
#define THREADS1 (WARPS_PER_BLOCK * 32)

__global__ __launch_bounds__(THREADS1)
void cosatt_scores_kernel(const float* __restrict__ query,
                          const float* __restrict__ keys,
                          float* __restrict__ scores)
{
    const int b    = blockIdx.y;
    const int warp = threadIdx.x >> 5;
    const int lane = threadIdx.x & 31;
    const int l    = blockIdx.x * WARPS_PER_BLOCK + warp;

    const float4* __restrict__ krow =
        reinterpret_cast<const float4*>(keys + ((size_t)b * L + l) * D);
    const float4* __restrict__ qrow =
        reinterpret_cast<const float4*>(query + (size_t)b * D);

    float dot = 0.f;
    float kk  = 0.f;

    // 256 float4 per row; 32 lanes x 8 iterations, fully unrolled ->
    // 8 independent LDG.128 in flight per lane. Keys are touch-once:
    // stream with evict-first (__ldcs) to keep L2 clean.
    #pragma unroll
    for (int i = 0; i < 8; ++i) {
        const int idx = i * 32 + lane;
        float4 kv = __ldcs(&krow[idx]);
        float4 qv = qrow[idx];          // L1/L2-resident, reused per block
        dot = fmaf(kv.x, qv.x, dot);
        dot = fmaf(kv.y, qv.y, dot);
        dot = fmaf(kv.z, qv.z, dot);
        dot = fmaf(kv.w, qv.w, dot);
        kk  = fmaf(kv.x, kv.x, kk);
        kk  = fmaf(kv.y, kv.y, kk);
        kk  = fmaf(kv.z, kv.z, kk);
        kk  = fmaf(kv.w, kv.w, kk);
    }

    #pragma unroll
    for (int off = 16; off > 0; off >>= 1) {
        dot += __shfl_xor_sync(0xffffffffu, dot, off);
        kk  += __shfl_xor_sync(0xffffffffu, kk,  off);
    }

    if (lane == 0) {
        float kn = fmaxf(sqrtf(kk), EPS);
        scores[(size_t)b * L + l] = dot / kn;
    }
}

#define THREADS2 1024
#define NWARP2 (THREADS2 / 32)

__global__ __launch_bounds__(THREADS2)
void cosatt_softmax_kernel(const float* __restrict__ query,
                           const int* __restrict__ mask,
                           float* __restrict__ scores /* in/out */)
{
    const int b   = blockIdx.x;
    const int tid = threadIdx.x;

    __shared__ float red[NWARP2];
    __shared__ float s_qn, s_max, s_sum;

    // ---- ||q|| : 1024 elems, 1 per thread ----
    {
        float qv = query[(size_t)b * D + tid];
        float qq = qv * qv;
        #pragma unroll
        for (int off = 16; off > 0; off >>= 1)
            qq += __shfl_xor_sync(0xffffffffu, qq, off);
        if ((tid & 31) == 0) red[tid >> 5] = qq;
        __syncthreads();
        if (tid < 32) {
            float v = (tid < NWARP2) ? red[tid] : 0.f;
            #pragma unroll
            for (int off = 16; off > 0; off >>= 1)
                v += __shfl_xor_sync(0xffffffffu, v, off);
            if (tid == 0) s_qn = fmaxf(sqrtf(v), EPS);
        }
        __syncthreads();
    }
    const float inv_qn = 1.0f / s_qn;

    // ---- load 4 scores + 4 mask vals per thread (vectorized) ----
    const float4* srow = reinterpret_cast<const float4*>(scores + (size_t)b * L);
    const int4*   mrow = reinterpret_cast<const int4*>(mask + (size_t)b * L);

    float4 sv = srow[tid];
    int4   mv = mrow[tid];

    float v0 = mv.x ? sv.x * inv_qn : -INFINITY;
    float v1 = mv.y ? sv.y * inv_qn : -INFINITY;
    float v2 = mv.z ? sv.z * inv_qn : -INFINITY;
    float v3 = mv.w ? sv.w * inv_qn : -INFINITY;

    // ---- block max ----
    float m = fmaxf(fmaxf(v0, v1), fmaxf(v2, v3));
    #pragma unroll
    for (int off = 16; off > 0; off >>= 1)
        m = fmaxf(m, __shfl_xor_sync(0xffffffffu, m, off));
    if ((tid & 31) == 0) red[tid >> 5] = m;
    __syncthreads();
    if (tid < 32) {
        float t = (tid < NWARP2) ? red[tid] : -INFINITY;
        #pragma unroll
        for (int off = 16; off > 0; off >>= 1)
            t = fmaxf(t, __shfl_xor_sync(0xffffffffu, t, off));
        if (tid == 0) s_max = t;
    }
    __syncthreads();
    const float row_max = s_max;

    // ---- exp + block sum ----
    v0 = __expf(v0 - row_max);
    v1 = __expf(v1 - row_max);
    v2 = __expf(v2 - row_max);
    v3 = __expf(v3 - row_max);
    float sum = (v0 + v1) + (v2 + v3);
    #pragma unroll
    for (int off = 16; off > 0; off >>= 1)
        sum += __shfl_xor_sync(0xffffffffu, sum, off);
    __syncthreads();   // safe reuse of red[]
    if ((tid & 31) == 0) red[tid >> 5] = sum;
    __syncthreads();
    if (tid < 32) {
        float t = (tid < NWARP2) ? red[tid] : 0.f;
        #pragma unroll
        for (int off = 16; off > 0; off >>= 1)
            t += __shfl_xor_sync(0xffffffffu, t, off);
        if (tid == 0) s_sum = t;
    }
    __syncthreads();
    const float inv_sum = 1.0f / s_sum;

    float4 o;
    o.x = v0 * inv_sum;
    o.y = v1 * inv_sum;
    o.z = v2 * inv_sum;
    o.w = v3 * inv_sum;
    reinterpret_cast<float4*>(scores + (size_t)b * L)[tid] = o;
}

extern "C" void kernel_launch(void* const* d_in, const int* in_sizes, int n_in,
                              void* d_out, int out_size)
{
    const float* query = nullptr;  // B*D   = 65536
    const float* keys  = nullptr;  // B*L*D = 268435456
    const int*   mask  = nullptr;  // B*L   = 262144 (int32)

    for (int i = 0; i < n_in; ++i) {
        if (in_sizes[i] == B * D)      query = (const float*)d_in[i];
        else if (in_sizes[i] == B * L) mask  = (const int*)d_in[i];
        else                           keys  = (const float*)d_in[i];
    }

    float* out = (float*)d_out;  // [B, L] float32

    dim3 grid1(L / WARPS_PER_BLOCK, B);
    cosatt_scores_kernel<<<grid1, THREADS1>>>(query, keys, out);
    cosatt_softmax_kernel<<<B, THREADS2>>>(query, mask, out);
}